// round 16
// baseline (speedup 1.0000x reference)
#include <cuda_runtime.h>
#include <cuda_bf16.h>
#include <math.h>

#define LO 3072
#define LC 1024
#define LT 4096   // LO + LC
#define DM 1024   // model dim
#define NH 16
#define DH 64
#define MH 4096

// ---------------- scratch (device globals; no allocation allowed) ----------------
__device__ float g_mod[12 * DM];          // [2 streams][6 chunks][1024]
__device__ float2 g_stat[LT];             // per-row (mean, inv) for current LN
__device__ float g_qkv[LT * 3 * DM];      // raw qkv fp32 (obs rows at 0, cond at LO*3*DM)
__device__ unsigned g_q[NH * LT * DH];    // [h][l][dh] tf32 words, q pre-scaled by 0.125*log2e
__device__ unsigned g_k[NH * LT * DH];    // tf32 words
__device__ unsigned g_v[NH * LT * DH];    // tf32 words
__device__ float g_attn[LT * DM];         // attention out fp32, global l order
__device__ float g_h[LT * MH];            // mlp hidden

// ---------------- helpers ----------------
__device__ __forceinline__ unsigned f2tf(float f) {
    unsigned u;
    asm("cvt.rna.tf32.f32 %0, %1;" : "=r"(u) : "f"(f));
    return u;
}

__device__ __forceinline__ float fexp2(float x) {
    float y;
    asm("ex2.approx.ftz.f32 %0, %1;" : "=f"(y) : "f"(x));
    return y;
}

__device__ __forceinline__ float ftanh(float x) {
    float y;
    asm("tanh.approx.f32 %0, %1;" : "=f"(y) : "f"(x));
    return y;
}

__device__ __forceinline__ void mma_tf32(float d[4], const unsigned a[4], const unsigned b[2]) {
    asm volatile(
        "mma.sync.aligned.m16n8k8.row.col.f32.tf32.tf32.f32 "
        "{%0,%1,%2,%3}, {%4,%5,%6,%7}, {%8,%9}, {%0,%1,%2,%3};"
        : "+f"(d[0]), "+f"(d[1]), "+f"(d[2]), "+f"(d[3])
        : "r"(a[0]), "r"(a[1]), "r"(a[2]), "r"(a[3]), "r"(b[0]), "r"(b[1]));
}

__device__ __forceinline__ void cp_async16(unsigned saddr, const void* g) {
    asm volatile("cp.async.cg.shared.global [%0], [%1], 16;" :: "r"(saddr), "l"(g));
}

// ---------------- modulation: silu(vec) @ mod_w + mod_b (K-split, 192 blocks) ----------------
__global__ __launch_bounds__(256) void mod_kernel(
    const float* __restrict__ vec,
    const float* __restrict__ ow, const float* __restrict__ ob,
    const float* __restrict__ cw, const float* __restrict__ cb) {
    __shared__ float sv[DM];
    __shared__ float part[256];
    int tid = threadIdx.x;
    for (int i = tid; i < DM; i += 256) {
        float v = vec[i];
        sv[i] = v / (1.0f + expf(-v));
    }
    __syncthreads();
    int j0 = blockIdx.x * 64;                 // 0..12287 step 64
    int stream = j0 / (6 * DM);
    int jbase = j0 % (6 * DM);
    int jl = tid & 63;
    int kc = tid >> 6;                        // 0..3
    int jj = jbase + jl;
    const float* w = stream ? cw : ow;
    const float* wp = w + (size_t)(kc * 256) * (6 * DM) + jj;
    const float* svp = sv + kc * 256;
    float acc = 0.0f;
#pragma unroll 8
    for (int k = 0; k < 256; k++)
        acc += svp[k] * wp[(size_t)k * (6 * DM)];
    part[tid] = acc;
    __syncthreads();
    if (kc == 0) {
        const float* b = stream ? cb : ob;
        float s = part[tid] + part[tid + 64] + part[tid + 128] + part[tid + 192];
        g_mod[stream * 6 * DM + jbase + jl] = s + b[jj];
    }
}

// ---------------- LN stats only: per-row (mean, inv) -> g_stat ----------------
__global__ void ln_stats_kernel(const float* __restrict__ x1, const float* __restrict__ x2) {
    int row = blockIdx.x;
    int tid = threadIdx.x;
    const float* xr = (row >= LO) ? (x2 + (size_t)(row - LO) * DM) : (x1 + (size_t)row * DM);
    __shared__ float ws[8], wss[8];
    float s = 0.0f, ss = 0.0f;
#pragma unroll
    for (int i = 0; i < 4; i++) {
        float v = xr[tid + i * 256];
        s += v; ss += v * v;
    }
#pragma unroll
    for (int off = 16; off > 0; off >>= 1) {
        s += __shfl_xor_sync(0xffffffffu, s, off);
        ss += __shfl_xor_sync(0xffffffffu, ss, off);
    }
    if ((tid & 31) == 0) { ws[tid >> 5] = s; wss[tid >> 5] = ss; }
    __syncthreads();
    if (tid == 0) {
        float S = 0.0f, SS = 0.0f;
#pragma unroll
        for (int i = 0; i < 8; i++) { S += ws[i]; SS += wss[i]; }
        float mean = S * (1.0f / DM);
        float var = SS * (1.0f / DM) - mean * mean;
        g_stat[row] = make_float2(mean, rsqrtf(var + 1e-6f));
    }
}

// ---------------- tf32 tensor-core GEMM, merged obs/cond pair, optional fused-LN A-load ----------------
// BM=128, BN=128, BK=32; 8 warps in 2x4; warp tile 64x32; mma m16n8k8.
// mode 0: C = AB (+bias)    mode 1: C = resid + gate*(AB + bias)
// mode 2: C = gelu_tanh(AB + bias)
// If st != null (per stream): A-load applies (x - mean)*inv*(1+sc[c]) + sh[c].
__global__ __launch_bounds__(256) void mma_gemm2_kernel(
    const float* __restrict__ A1, const float* __restrict__ B1, float* __restrict__ C1,
    const float* __restrict__ A2, const float* __restrict__ B2, float* __restrict__ C2,
    int M1, int N, int K,
    const float* __restrict__ bias1, const float* __restrict__ bias2,
    const float* __restrict__ resid1, const float* __restrict__ resid2,
    int gidx1, int gidx2, int mode,
    const float2* __restrict__ st1, const float2* __restrict__ st2,
    const float* __restrict__ sh1, const float* __restrict__ sc1,
    const float* __restrict__ sh2, const float* __restrict__ sc2) {
    __shared__ unsigned As[128][36];   // row-major, pad 4
    __shared__ unsigned Bs[32][136];   // k-major,   pad 8

    int tid = threadIdx.x;
    int lane = tid & 31, warp = tid >> 5;
    int wm = warp >> 2, wn = warp & 3;          // 2 x 4 warp grid
    int g = lane >> 2, tg = lane & 3;
    int by = blockIdx.y * 128, col0 = blockIdx.x * 128;

    const float *A, *B, *bias, *resid, *lsh, *lsc;
    const float2* st;
    float* C;
    int gidx, row0;
    if (by < M1) { A = A1; B = B1; C = C1; bias = bias1; resid = resid1; gidx = gidx1;
                   st = st1; lsh = sh1; lsc = sc1; row0 = by; }
    else         { A = A2; B = B2; C = C2; bias = bias2; resid = resid2; gidx = gidx2;
                   st = st2; lsh = sh2; lsc = sc2; row0 = by - M1; }

    float acc[16][4];
#pragma unroll
    for (int i = 0; i < 16; i++)
#pragma unroll
        for (int j = 0; j < 4; j++) acc[i][j] = 0.0f;

    for (int k0 = 0; k0 < K; k0 += 32) {
#pragma unroll
        for (int i = 0; i < 4; i++) {
            int idx = tid + i * 256;
            int r = idx >> 3, c4 = (idx & 7) << 2;
            float4 v = *(const float4*)&A[(size_t)(row0 + r) * K + k0 + c4];
            if (st) {
                float2 s2 = st[row0 + r];
                float4 scv = *(const float4*)&lsc[k0 + c4];
                float4 shv = *(const float4*)&lsh[k0 + c4];
                v.x = (v.x - s2.x) * s2.y * (1.0f + scv.x) + shv.x;
                v.y = (v.y - s2.x) * s2.y * (1.0f + scv.y) + shv.y;
                v.z = (v.z - s2.x) * s2.y * (1.0f + scv.z) + shv.z;
                v.w = (v.w - s2.x) * s2.y * (1.0f + scv.w) + shv.w;
            }
            As[r][c4 + 0] = f2tf(v.x); As[r][c4 + 1] = f2tf(v.y);
            As[r][c4 + 2] = f2tf(v.z); As[r][c4 + 3] = f2tf(v.w);
        }
#pragma unroll
        for (int i = 0; i < 4; i++) {
            int idx = tid + i * 256;
            int r = idx >> 5, c4 = (idx & 31) << 2;
            float4 v = *(const float4*)&B[(size_t)(k0 + r) * N + col0 + c4];
            Bs[r][c4 + 0] = f2tf(v.x); Bs[r][c4 + 1] = f2tf(v.y);
            Bs[r][c4 + 2] = f2tf(v.z); Bs[r][c4 + 3] = f2tf(v.w);
        }
        __syncthreads();
#pragma unroll
        for (int k8 = 0; k8 < 4; k8++) {
            unsigned a[4][4], b[4][2];
#pragma unroll
            for (int mt = 0; mt < 4; mt++) {
                int r = wm * 64 + mt * 16;
                a[mt][0] = As[r + g][k8 * 8 + tg];
                a[mt][1] = As[r + 8 + g][k8 * 8 + tg];
                a[mt][2] = As[r + g][k8 * 8 + tg + 4];
                a[mt][3] = As[r + 8 + g][k8 * 8 + tg + 4];
            }
#pragma unroll
            for (int nt = 0; nt < 4; nt++) {
                int c = wn * 32 + nt * 8 + g;
                b[nt][0] = Bs[k8 * 8 + tg][c];
                b[nt][1] = Bs[k8 * 8 + tg + 4][c];
            }
#pragma unroll
            for (int mt = 0; mt < 4; mt++)
#pragma unroll
                for (int nt = 0; nt < 4; nt++)
                    mma_tf32(acc[mt * 4 + nt], a[mt], b[nt]);
        }
        __syncthreads();
    }

    const float* gate = (gidx >= 0) ? (g_mod + gidx * DM) : nullptr;
#pragma unroll
    for (int mt = 0; mt < 4; mt++) {
#pragma unroll
        for (int nt = 0; nt < 4; nt++) {
            int c = col0 + wn * 32 + nt * 8 + 2 * tg;
#pragma unroll
            for (int half = 0; half < 2; half++) {
                int r = row0 + wm * 64 + mt * 16 + g + half * 8;
#pragma unroll
                for (int jj = 0; jj < 2; jj++) {
                    int cc = c + jj;
                    float v = acc[mt * 4 + nt][half * 2 + jj];
                    if (bias) v += bias[cc];
                    if (mode == 1) {
                        v = resid[(size_t)r * N + cc] + gate[cc] * v;
                    } else if (mode == 2) {
                        float t = v;
                        v = 0.5f * t * (1.0f + ftanh(0.7978845608f * (t + 0.044715f * t * t * t)));
                    }
                    C[(size_t)r * N + cc] = v;
                }
            }
        }
    }
}

// ---------------- qkv post: 1 warp per (token, head); shuffle rmsnorm, paired rope ----------------
// block (32, 8): warp y handles heads y*2 + {0,1} for token gl. Lane holds dh pair (2*lane, 2*lane+1).
__global__ __launch_bounds__(256) void qkv_post_kernel(const float* __restrict__ pe,
                                const float* __restrict__ oqs, const float* __restrict__ oks,
                                const float* __restrict__ cqs, const float* __restrict__ cks) {
    int gl = blockIdx.x;      // global token (cond first)
    int lane = threadIdx.x;   // 0..31
    int y = threadIdx.y;      // 0..7
    bool is_cond = gl < LC;
    const float* src = is_cond ? (g_qkv + (size_t)LO * 3 * DM + (size_t)gl * 3 * DM)
                               : (g_qkv + (size_t)(gl - LC) * 3 * DM);
    const float* qs = is_cond ? cqs : oqs;
    const float* ks = is_cond ? cks : oks;
    float4 pp = *(const float4*)&pe[(size_t)gl * 128 + lane * 4];
    float qs0 = qs[2 * lane], qs1 = qs[2 * lane + 1];
    float ks0 = ks[2 * lane], ks1 = ks[2 * lane + 1];
#pragma unroll
    for (int hh = 0; hh < 2; hh++) {
        int h = y * 2 + hh;
        float2 q2 = *(const float2*)&src[h * DH + 2 * lane];
        float2 k2 = *(const float2*)&src[DM + h * DH + 2 * lane];
        float2 v2 = *(const float2*)&src[2 * DM + h * DH + 2 * lane];
        float qss = q2.x * q2.x + q2.y * q2.y;
        float kss = k2.x * k2.x + k2.y * k2.y;
#pragma unroll
        for (int off = 16; off > 0; off >>= 1) {
            qss += __shfl_xor_sync(0xffffffffu, qss, off);
            kss += __shfl_xor_sync(0xffffffffu, kss, off);
        }
        float qinv = rsqrtf(qss * (1.0f / DH) + 1e-6f);
        float kinv = rsqrtf(kss * (1.0f / DH) + 1e-6f);
        float qn0 = q2.x * qinv * qs0, qn1 = q2.y * qinv * qs1;
        float kn0 = k2.x * kinv * ks0, kn1 = k2.y * kinv * ks1;
        float qo0 = pp.x * qn0 + pp.y * qn1;
        float qo1 = pp.z * qn0 + pp.w * qn1;
        float ko0 = pp.x * kn0 + pp.y * kn1;
        float ko1 = pp.z * kn0 + pp.w * kn1;
        size_t oidx = ((size_t)h * LT + gl) * DH + 2 * lane;
        // q pre-scaled by 0.125 * log2(e) so softmax can use raw ex2
        *(uint2*)&g_q[oidx] = make_uint2(f2tf(qo0 * 0.18033688f), f2tf(qo1 * 0.18033688f));
        *(uint2*)&g_k[oidx] = make_uint2(f2tf(ko0), f2tf(ko1));
        *(uint2*)&g_v[oidx] = make_uint2(f2tf(v2.x), f2tf(v2.y));
    }
}

// ---------------- attention: flash w/ tf32 mma, in-register softmax, cp.async K/V pipeline ----------------
// 8 warps in 4x2 (wm: 32 q-rows each, wn: 32 cols each). mma m16n8k8. Scores in log2 domain.
#define AS 68   // padded row stride (u32 words)
__global__ __launch_bounds__(256, 2) void attn_mma_kernel() {
    extern __shared__ unsigned smu[];
    unsigned* Qs = smu;                    // [128][AS] tf32
    unsigned* Ks = Qs + 128 * AS;          // [64][AS]  tf32
    unsigned* Vs = Ks + 64 * AS;           // [64][AS]  tf32
    unsigned* Psu = Vs + 64 * AS;          // [128][AS] tf32 probabilities
    float* row_m = (float*)(Psu + 128 * AS);   // [128]
    float* row_l = row_m + 128;                // [128]
    float* wmax = row_l + 128;                 // [2][128] per-warp row max
    float* wsum = wmax + 256;                  // [2][128] per-warp row sum

    int h = blockIdx.x;
    int q0 = blockIdx.y * 128;
    int tid = threadIdx.x;
    int lane = tid & 31, warp = tid >> 5;
    int wm = warp >> 1, wn = warp & 1;     // 4 x 2
    int g = lane >> 2, tg = lane & 3;

    const unsigned* qb = g_q + ((size_t)h * LT + q0) * DH;
    const unsigned* kb = g_k + (size_t)h * LT * DH;
    const unsigned* vb = g_v + (size_t)h * LT * DH;

    unsigned ks_sm = (unsigned)__cvta_generic_to_shared(Ks);
    unsigned vs_sm = (unsigned)__cvta_generic_to_shared(Vs);
    int ld_r = tid >> 4, ld_c = (tid & 15) << 2;

    // load Q tile: 128 rows x 64 words = 2048 uint4 slots
#pragma unroll
    for (int i = 0; i < 8; i++) {
        int idx = tid + i * 256;
        int r = idx >> 4, c = (idx & 15) << 2;
        *(uint4*)&Qs[r * AS + c] = *(const uint4*)&qb[(size_t)r * DH + c];
    }
    if (tid < 128) { row_m[tid] = -3e38f; row_l[tid] = 0.0f; }

    // prologue: async K0, V0 (separate commit groups)
#pragma unroll
    for (int i = 0; i < 4; i++) {
        int r = ld_r + i * 16;
        cp_async16(ks_sm + (r * AS + ld_c) * 4, &kb[(size_t)r * DH + ld_c]);
    }
    asm volatile("cp.async.commit_group;" ::: "memory");
#pragma unroll
    for (int i = 0; i < 4; i++) {
        int r = ld_r + i * 16;
        cp_async16(vs_sm + (r * AS + ld_c) * 4, &vb[(size_t)r * DH + ld_c]);
    }
    asm volatile("cp.async.commit_group;" ::: "memory");

    float acc_o[2][4][4];
#pragma unroll
    for (int mt = 0; mt < 2; mt++)
#pragma unroll
        for (int nt = 0; nt < 4; nt++)
#pragma unroll
            for (int j = 0; j < 4; j++) acc_o[mt][nt][j] = 0.0f;

    for (int kt = 0; kt < LT; kt += 64) {
        int ktn = (kt + 64 < LT) ? kt + 64 : 0;

        asm volatile("cp.async.wait_group 1;" ::: "memory");   // K(t) done
        __syncthreads();                                        // [top] K visible; Psu free

        // ---- S = Q K^T (log2 domain; q pre-scaled) ----
        float acc_s[2][4][4];
#pragma unroll
        for (int mt = 0; mt < 2; mt++)
#pragma unroll
            for (int nt = 0; nt < 4; nt++)
#pragma unroll
                for (int j = 0; j < 4; j++) acc_s[mt][nt][j] = 0.0f;
#pragma unroll
        for (int k8 = 0; k8 < 8; k8++) {
            unsigned a[2][4], b[4][2];
#pragma unroll
            for (int mt = 0; mt < 2; mt++) {
                int r = wm * 32 + mt * 16;
                a[mt][0] = Qs[(r + g) * AS + k8 * 8 + tg];
                a[mt][1] = Qs[(r + 8 + g) * AS + k8 * 8 + tg];
                a[mt][2] = Qs[(r + g) * AS + k8 * 8 + tg + 4];
                a[mt][3] = Qs[(r + 8 + g) * AS + k8 * 8 + tg + 4];
            }
#pragma unroll
            for (int nt = 0; nt < 4; nt++) {
                int c = wn * 32 + nt * 8 + g;
                b[nt][0] = Ks[c * AS + k8 * 8 + tg];
                b[nt][1] = Ks[c * AS + k8 * 8 + tg + 4];
            }
#pragma unroll
            for (int mt = 0; mt < 2; mt++)
#pragma unroll
                for (int nt = 0; nt < 4; nt++)
                    mma_tf32(acc_s[mt][nt], a[mt], b[nt]);
        }

        // ---- per-warp row max via shuffles over tg lanes ----
#pragma unroll
        for (int mt = 0; mt < 2; mt++)
#pragma unroll
            for (int half = 0; half < 2; half++) {
                float m = acc_s[mt][0][half * 2];
#pragma unroll
                for (int nt = 0; nt < 4; nt++) {
                    m = fmaxf(m, acc_s[mt][nt][half * 2 + 0]);
                    m = fmaxf(m, acc_s[mt][nt][half * 2 + 1]);
                }
                m = fmaxf(m, __shfl_xor_sync(0xffffffffu, m, 1));
                m = fmaxf(m, __shfl_xor_sync(0xffffffffu, m, 2));
                if (tg == 0) wmax[wn * 128 + wm * 32 + mt * 16 + half * 8 + g] = m;
            }
        __syncthreads();                                        // [A] wmax ready; Ks free

        // issue K(t+1) (overlaps softmax + PV)
#pragma unroll
        for (int i = 0; i < 4; i++) {
            int r = ld_r + i * 16;
            cp_async16(ks_sm + (r * AS + ld_c) * 4, &kb[(size_t)(ktn + r) * DH + ld_c]);
        }
        asm volatile("cp.async.commit_group;" ::: "memory");

        // ---- in-register softmax: exp2, P -> tf32 smem, row sums via shuffles ----
        float mnew[2][2], corr[2][2];
#pragma unroll
        for (int mt = 0; mt < 2; mt++)
#pragma unroll
            for (int half = 0; half < 2; half++) {
                int r = wm * 32 + mt * 16 + half * 8 + g;
                float mo = row_m[r];
                float mn = fmaxf(mo, fmaxf(wmax[r], wmax[128 + r]));
                float cr = fexp2(mo - mn);
                mnew[mt][half] = mn; corr[mt][half] = cr;
                float ps = 0.0f;
#pragma unroll
                for (int nt = 0; nt < 4; nt++) {
                    float p0 = fexp2(acc_s[mt][nt][half * 2 + 0] - mn);
                    float p1 = fexp2(acc_s[mt][nt][half * 2 + 1] - mn);
                    ps += p0 + p1;
                    int c = wn * 32 + nt * 8 + 2 * tg;
                    Psu[r * AS + c]     = f2tf(p0);
                    Psu[r * AS + c + 1] = f2tf(p1);
                }
                ps += __shfl_xor_sync(0xffffffffu, ps, 1);
                ps += __shfl_xor_sync(0xffffffffu, ps, 2);
                if (tg == 0) wsum[wn * 128 + r] = ps;
                // rescale O
#pragma unroll
                for (int nt = 0; nt < 4; nt++) {
                    acc_o[mt][nt][half * 2 + 0] *= cr;
                    acc_o[mt][nt][half * 2 + 1] *= cr;
                }
            }
        asm volatile("cp.async.wait_group 1;" ::: "memory");   // V(t) done (K(t+1) pends)
        __syncthreads();                                        // [B] Psu/wsum complete, V visible

        // designated lanes update running stats (overlaps PV mma on other lanes)
        if (wn == 0 && tg == 0) {
#pragma unroll
            for (int mt = 0; mt < 2; mt++)
#pragma unroll
                for (int half = 0; half < 2; half++) {
                    int r = wm * 32 + mt * 16 + half * 8 + g;
                    row_l[r] = row_l[r] * corr[mt][half] + wsum[r] + wsum[128 + r];
                    row_m[r] = mnew[mt][half];
                }
        }

        // ---- O += P V ----
#pragma unroll
        for (int k8 = 0; k8 < 8; k8++) {
            unsigned a[2][4], b[4][2];
#pragma unroll
            for (int mt = 0; mt < 2; mt++) {
                int r = wm * 32 + mt * 16;
                a[mt][0] = Psu[(r + g) * AS + k8 * 8 + tg];
                a[mt][1] = Psu[(r + 8 + g) * AS + k8 * 8 + tg];
                a[mt][2] = Psu[(r + g) * AS + k8 * 8 + tg + 4];
                a[mt][3] = Psu[(r + 8 + g) * AS + k8 * 8 + tg + 4];
            }
#pragma unroll
            for (int nt = 0; nt < 4; nt++) {
                int c = wn * 32 + nt * 8 + g;          // output col (d)
                b[nt][0] = Vs[(k8 * 8 + tg) * AS + c];
                b[nt][1] = Vs[(k8 * 8 + tg + 4) * AS + c];
            }
#pragma unroll
            for (int mt = 0; mt < 2; mt++)
#pragma unroll
                for (int nt = 0; nt < 4; nt++)
                    mma_tf32(acc_o[mt][nt], a[mt], b[nt]);
        }
        __syncthreads();                            // [C] Vs reads done

        // issue V(t+1) (overlaps next tile's S-mma)
#pragma unroll
        for (int i = 0; i < 4; i++) {
            int r = ld_r + i * 16;
            cp_async16(vs_sm + (r * AS + ld_c) * 4, &vb[(size_t)(ktn + r) * DH + ld_c]);
        }
        asm volatile("cp.async.commit_group;" ::: "memory");
    }
    asm volatile("cp.async.wait_group 0;" ::: "memory");
    __syncthreads();

    // epilogue: normalize by row_l, write out
#pragma unroll
    for (int mt = 0; mt < 2; mt++)
#pragma unroll
        for (int half = 0; half < 2; half++) {
            int r = wm * 32 + mt * 16 + half * 8 + g;
            float inv = 1.0f / row_l[r];
#pragma unroll
            for (int nt = 0; nt < 4; nt++) {
                int c = wn * 32 + nt * 8 + 2 * tg;
                float* dst = &g_attn[(size_t)(q0 + r) * DM + h * DH + c];
                dst[0] = acc_o[mt][nt][half * 2 + 0] * inv;
                dst[1] = acc_o[mt][nt][half * 2 + 1] * inv;
            }
        }
}

// ---------------- launch ----------------
extern "C" void kernel_launch(void* const* d_in, const int* in_sizes, int n_in,
                              void* d_out, int out_size) {
    const float* obs   = (const float*)d_in[0];
    const float* cond  = (const float*)d_in[1];
    const float* vec   = (const float*)d_in[2];
    const float* pe    = (const float*)d_in[3];
    const float* o_mod_w = (const float*)d_in[4];
    const float* o_mod_b = (const float*)d_in[5];
    const float* o_qkv_w = (const float*)d_in[6];
    const float* o_q_s   = (const float*)d_in[7];
    const float* o_k_s   = (const float*)d_in[8];
    const float* o_proj_w = (const float*)d_in[9];
    const float* o_proj_b = (const float*)d_in[10];
    const float* o_mlp_w1 = (const float*)d_in[11];
    const float* o_mlp_b1 = (const float*)d_in[12];
    const float* o_mlp_w2 = (const float*)d_in[13];
    const float* o_mlp_b2 = (const float*)d_in[14];
    const float* c_mod_w = (const float*)d_in[15];
    const float* c_mod_b = (const float*)d_in[16];
    const float* c_qkv_w = (const float*)d_in[17];
    const float* c_q_s   = (const float*)d_in[18];
    const float* c_k_s   = (const float*)d_in[19];
    const float* c_proj_w = (const float*)d_in[20];
    const float* c_proj_b = (const float*)d_in[21];
    const float* c_mlp_w1 = (const float*)d_in[22];
    const float* c_mlp_b1 = (const float*)d_in[23];
    const float* c_mlp_w2 = (const float*)d_in[24];
    const float* c_mlp_b2 = (const float*)d_in[25];

    float* out = (float*)d_out;
    float* out_obs = out;                 // rows 0..LO-1
    float* out_cond = out + (size_t)LO * DM;

    float *p_qkv, *p_attn, *p_h, *p_mod;
    float2* p_stat;
    cudaGetSymbolAddress((void**)&p_qkv, g_qkv);
    cudaGetSymbolAddress((void**)&p_attn, g_attn);
    cudaGetSymbolAddress((void**)&p_h, g_h);
    cudaGetSymbolAddress((void**)&p_mod, g_mod);
    cudaGetSymbolAddress((void**)&p_stat, g_stat);

    int smem_bytes = (int)((384 * AS) * 4 + (128 + 128 + 256 + 256) * 4);
    static int init = 0;
    if (!init) {
        init = 1;
        cudaFuncSetAttribute(attn_mma_kernel, cudaFuncAttributeMaxDynamicSharedMemorySize, smem_bytes);
    }

    // 1. modulation vectors (K-split for parallelism)
    mod_kernel<<<192, 256>>>(vec, o_mod_w, o_mod_b, c_mod_w, c_mod_b);

    // 2. LN1 stats (mean, inv per row)
    ln_stats_kernel<<<LT, 256>>>(obs, cond);

    // 3. qkv GEMMs, merged, LN1 fused into A-load (obs: chunks 0/1; cond: chunks 6/7)
    {
        dim3 g(3 * DM / 128, LT / 128);
        mma_gemm2_kernel<<<g, 256>>>(obs, o_qkv_w, p_qkv,
                                     cond, c_qkv_w, p_qkv + (size_t)LO * 3 * DM,
                                     LO, 3 * DM, DM,
                                     nullptr, nullptr, nullptr, nullptr, -1, -1, 0,
                                     p_stat, p_stat + LO,
                                     p_mod + 0 * DM, p_mod + 1 * DM,
                                     p_mod + 6 * DM, p_mod + 7 * DM);
    }

    // 4. rmsnorm + rope + scatter (tf32 pre-converted, warp-per-head)
    {
        dim3 b(32, 8);
        qkv_post_kernel<<<LT, b>>>(pe, o_q_s, o_k_s, c_q_s, c_k_s);
    }

    // 5. attention (tensor-core flash, cp.async pipelined, in-register softmax)
    {
        dim3 g(NH, LT / 128);
        attn_mma_kernel<<<g, 256, smem_bytes>>>();
    }

    // 6. proj + gated residual (gate1 = chunk 2), merged
    {
        dim3 g(DM / 128, LT / 128);
        mma_gemm2_kernel<<<g, 256>>>(p_attn + (size_t)LC * DM, o_proj_w, out_obs,
                                     p_attn, c_proj_w, out_cond,
                                     LO, DM, DM,
                                     o_proj_b, c_proj_b, obs, cond, 0 * 6 + 2, 1 * 6 + 2, 1,
                                     nullptr, nullptr, nullptr, nullptr, nullptr, nullptr);
    }

    // 7. LN2 stats from proj output
    ln_stats_kernel<<<LT, 256>>>(out_obs, out_cond);

    // 8. mlp1 + gelu, merged, LN2 fused into A-load (obs: chunks 3/4; cond: chunks 9/10)
    {
        dim3 g(MH / 128, LT / 128);
        mma_gemm2_kernel<<<g, 256>>>(out_obs, o_mlp_w1, p_h,
                                     out_cond, c_mlp_w1, p_h + (size_t)LO * MH,
                                     LO, MH, DM,
                                     o_mlp_b1, c_mlp_b1, nullptr, nullptr, -1, -1, 2,
                                     p_stat, p_stat + LO,
                                     p_mod + 3 * DM, p_mod + 4 * DM,
                                     p_mod + 9 * DM, p_mod + 10 * DM);
    }

    // 9. mlp2 + gated residual (gate2 = chunk 5), merged, in-place residual on d_out
    {
        dim3 g(DM / 128, LT / 128);
        mma_gemm2_kernel<<<g, 256>>>(p_h, o_mlp_w2, out_obs,
                                     p_h + (size_t)LO * MH, c_mlp_w2, out_cond,
                                     LO, DM, MH,
                                     o_mlp_b2, c_mlp_b2, out_obs, out_cond, 0 * 6 + 5, 1 * 6 + 5, 1,
                                     nullptr, nullptr, nullptr, nullptr, nullptr, nullptr);
    }
}

// round 17
// speedup vs baseline: 1.2134x; 1.2134x over previous
#include <cuda_runtime.h>
#include <cuda_bf16.h>
#include <math.h>

#define LO 3072
#define LC 1024
#define LT 4096   // LO + LC
#define DM 1024   // model dim
#define NH 16
#define DH 64
#define MH 4096

// ---------------- scratch (device globals; no allocation allowed) ----------------
__device__ float g_mod[12 * DM];          // [2 streams][6 chunks][1024]
__device__ float g_xm[LT * DM];           // modulated LN output (obs rows 0..LO-1, cond at LO)
__device__ float g_qkv[LT * 3 * DM];      // raw qkv (obs rows at 0, cond rows at LO*3*DM)
__device__ unsigned g_q[NH * LT * DH];    // [h][l][dh] tf32 words, q pre-scaled by 0.125*log2e
__device__ unsigned g_k[NH * LT * DH];    // tf32 words
__device__ unsigned g_v[NH * LT * DH];    // tf32 words
__device__ float g_attn[LT * DM];         // attention out fp32, global l order
__device__ float g_h[LT * MH];            // mlp hidden

// ---------------- helpers ----------------
__device__ __forceinline__ unsigned f2tf(float f) {
    unsigned u;
    asm("cvt.rna.tf32.f32 %0, %1;" : "=r"(u) : "f"(f));
    return u;
}

__device__ __forceinline__ float fexp2(float x) {
    float y;
    asm("ex2.approx.ftz.f32 %0, %1;" : "=f"(y) : "f"(x));
    return y;
}

__device__ __forceinline__ float ftanh(float x) {
    float y;
    asm("tanh.approx.f32 %0, %1;" : "=f"(y) : "f"(x));
    return y;
}

__device__ __forceinline__ void mma_tf32(float d[4], const unsigned a[4], const unsigned b[2]) {
    asm volatile(
        "mma.sync.aligned.m16n8k8.row.col.f32.tf32.tf32.f32 "
        "{%0,%1,%2,%3}, {%4,%5,%6,%7}, {%8,%9}, {%0,%1,%2,%3};"
        : "+f"(d[0]), "+f"(d[1]), "+f"(d[2]), "+f"(d[3])
        : "r"(a[0]), "r"(a[1]), "r"(a[2]), "r"(a[3]), "r"(b[0]), "r"(b[1]));
}

__device__ __forceinline__ void cp_async16(unsigned saddr, const void* g) {
    asm volatile("cp.async.cg.shared.global [%0], [%1], 16;" :: "r"(saddr), "l"(g));
}

// ---------------- modulation: silu(vec) @ mod_w + mod_b (K-split, 192 blocks) ----------------
__global__ __launch_bounds__(256) void mod_kernel(
    const float* __restrict__ vec,
    const float* __restrict__ ow, const float* __restrict__ ob,
    const float* __restrict__ cw, const float* __restrict__ cb) {
    __shared__ float sv[DM];
    __shared__ float part[256];
    int tid = threadIdx.x;
    for (int i = tid; i < DM; i += 256) {
        float v = vec[i];
        sv[i] = v / (1.0f + expf(-v));
    }
    __syncthreads();
    int j0 = blockIdx.x * 64;                 // 0..12287 step 64
    int stream = j0 / (6 * DM);
    int jbase = j0 % (6 * DM);
    int jl = tid & 63;
    int kc = tid >> 6;                        // 0..3
    int jj = jbase + jl;
    const float* w = stream ? cw : ow;
    const float* wp = w + (size_t)(kc * 256) * (6 * DM) + jj;
    const float* svp = sv + kc * 256;
    float acc = 0.0f;
#pragma unroll 8
    for (int k = 0; k < 256; k++)
        acc += svp[k] * wp[(size_t)k * (6 * DM)];
    part[tid] = acc;
    __syncthreads();
    if (kc == 0) {
        const float* b = stream ? cb : ob;
        float s = part[tid] + part[tid + 64] + part[tid + 128] + part[tid + 192];
        g_mod[stream * 6 * DM + jbase + jl] = s + b[jj];
    }
}

// ---------------- layernorm + modulation, merged obs/cond (shuffle reduce) ----------------
__global__ void ln_mod_kernel(const float* __restrict__ x1, const float* __restrict__ x2,
                              float* __restrict__ y, int shiftc, int scalec) {
    int row = blockIdx.x;
    int tid = threadIdx.x;
    int stream = (row >= LO);
    const float* xr = stream ? (x2 + (size_t)(row - LO) * DM) : (x1 + (size_t)row * DM);
    __shared__ float ws[8], wss[8];
    float s = 0.0f, ss = 0.0f;
    float xv[4];
#pragma unroll
    for (int i = 0; i < 4; i++) {
        float v = xr[tid + i * 256];
        xv[i] = v;
        s += v; ss += v * v;
    }
#pragma unroll
    for (int off = 16; off > 0; off >>= 1) {
        s += __shfl_xor_sync(0xffffffffu, s, off);
        ss += __shfl_xor_sync(0xffffffffu, ss, off);
    }
    if ((tid & 31) == 0) { ws[tid >> 5] = s; wss[tid >> 5] = ss; }
    __syncthreads();
    float S = 0.0f, SS = 0.0f;
#pragma unroll
    for (int i = 0; i < 8; i++) { S += ws[i]; SS += wss[i]; }
    float mean = S * (1.0f / DM);
    float var = SS * (1.0f / DM) - mean * mean;
    float inv = rsqrtf(var + 1e-6f);
    const float* sh = g_mod + (stream * 6 + shiftc) * DM;
    const float* sc = g_mod + (stream * 6 + scalec) * DM;
    float* yr = y + (size_t)row * DM;
#pragma unroll
    for (int i = 0; i < 4; i++) {
        int c = tid + i * 256;
        yr[c] = (xv[i] - mean) * inv * (1.0f + sc[c]) + sh[c];
    }
}

// ---------------- tf32 tensor-core GEMM, merged obs/cond pair ----------------
// BM=128, BN=128, BK=32; 8 warps in 2x4; warp tile 64x32; mma m16n8k8.
// mode 0: C = AB (+bias)    mode 1: C = resid + gate*(AB + bias)
// mode 2: C = gelu_tanh(AB + bias)
__global__ __launch_bounds__(256) void mma_gemm2_kernel(
    const float* __restrict__ A1, const float* __restrict__ B1, float* __restrict__ C1,
    const float* __restrict__ A2, const float* __restrict__ B2, float* __restrict__ C2,
    int M1, int N, int K,
    const float* __restrict__ bias1, const float* __restrict__ bias2,
    const float* __restrict__ resid1, const float* __restrict__ resid2,
    int gidx1, int gidx2, int mode) {
    __shared__ unsigned As[128][36];   // row-major, pad 4
    __shared__ unsigned Bs[32][136];   // k-major,   pad 8

    int tid = threadIdx.x;
    int lane = tid & 31, warp = tid >> 5;
    int wm = warp >> 2, wn = warp & 3;          // 2 x 4 warp grid
    int g = lane >> 2, tg = lane & 3;
    int by = blockIdx.y * 128, col0 = blockIdx.x * 128;

    const float *A, *B, *bias, *resid;
    float* C;
    int gidx, row0;
    if (by < M1) { A = A1; B = B1; C = C1; bias = bias1; resid = resid1; gidx = gidx1; row0 = by; }
    else         { A = A2; B = B2; C = C2; bias = bias2; resid = resid2; gidx = gidx2; row0 = by - M1; }

    float acc[16][4];
#pragma unroll
    for (int i = 0; i < 16; i++)
#pragma unroll
        for (int j = 0; j < 4; j++) acc[i][j] = 0.0f;

    for (int k0 = 0; k0 < K; k0 += 32) {
#pragma unroll
        for (int i = 0; i < 4; i++) {
            int idx = tid + i * 256;
            int r = idx >> 3, c4 = (idx & 7) << 2;
            float4 v = *(const float4*)&A[(size_t)(row0 + r) * K + k0 + c4];
            As[r][c4 + 0] = f2tf(v.x); As[r][c4 + 1] = f2tf(v.y);
            As[r][c4 + 2] = f2tf(v.z); As[r][c4 + 3] = f2tf(v.w);
        }
#pragma unroll
        for (int i = 0; i < 4; i++) {
            int idx = tid + i * 256;
            int r = idx >> 5, c4 = (idx & 31) << 2;
            float4 v = *(const float4*)&B[(size_t)(k0 + r) * N + col0 + c4];
            Bs[r][c4 + 0] = f2tf(v.x); Bs[r][c4 + 1] = f2tf(v.y);
            Bs[r][c4 + 2] = f2tf(v.z); Bs[r][c4 + 3] = f2tf(v.w);
        }
        __syncthreads();
#pragma unroll
        for (int k8 = 0; k8 < 4; k8++) {
            unsigned a[4][4], b[4][2];
#pragma unroll
            for (int mt = 0; mt < 4; mt++) {
                int r = wm * 64 + mt * 16;
                a[mt][0] = As[r + g][k8 * 8 + tg];
                a[mt][1] = As[r + 8 + g][k8 * 8 + tg];
                a[mt][2] = As[r + g][k8 * 8 + tg + 4];
                a[mt][3] = As[r + 8 + g][k8 * 8 + tg + 4];
            }
#pragma unroll
            for (int nt = 0; nt < 4; nt++) {
                int c = wn * 32 + nt * 8 + g;
                b[nt][0] = Bs[k8 * 8 + tg][c];
                b[nt][1] = Bs[k8 * 8 + tg + 4][c];
            }
#pragma unroll
            for (int mt = 0; mt < 4; mt++)
#pragma unroll
                for (int nt = 0; nt < 4; nt++)
                    mma_tf32(acc[mt * 4 + nt], a[mt], b[nt]);
        }
        __syncthreads();
    }

    const float* gate = (gidx >= 0) ? (g_mod + gidx * DM) : nullptr;
#pragma unroll
    for (int mt = 0; mt < 4; mt++) {
#pragma unroll
        for (int nt = 0; nt < 4; nt++) {
            int c = col0 + wn * 32 + nt * 8 + 2 * tg;
#pragma unroll
            for (int half = 0; half < 2; half++) {
                int r = row0 + wm * 64 + mt * 16 + g + half * 8;
#pragma unroll
                for (int jj = 0; jj < 2; jj++) {
                    int cc = c + jj;
                    float v = acc[mt * 4 + nt][half * 2 + jj];
                    if (bias) v += bias[cc];
                    if (mode == 1) {
                        v = resid[(size_t)r * N + cc] + gate[cc] * v;
                    } else if (mode == 2) {
                        float t = v;
                        v = 0.5f * t * (1.0f + ftanh(0.7978845608f * (t + 0.044715f * t * t * t)));
                    }
                    C[(size_t)r * N + cc] = v;
                }
            }
        }
    }
}

// ---------------- qkv post: 1 warp per (token, head); shuffle rmsnorm, paired rope ----------------
// block (32, 8): warp y handles heads y*2 + {0,1} for token gl. Lane holds dh pair (2*lane, 2*lane+1).
__global__ __launch_bounds__(256) void qkv_post_kernel(const float* __restrict__ pe,
                                const float* __restrict__ oqs, const float* __restrict__ oks,
                                const float* __restrict__ cqs, const float* __restrict__ cks) {
    int gl = blockIdx.x;      // global token (cond first)
    int lane = threadIdx.x;   // 0..31
    int y = threadIdx.y;      // 0..7
    bool is_cond = gl < LC;
    const float* src = is_cond ? (g_qkv + (size_t)LO * 3 * DM + (size_t)gl * 3 * DM)
                               : (g_qkv + (size_t)(gl - LC) * 3 * DM);
    const float* qs = is_cond ? cqs : oqs;
    const float* ks = is_cond ? cks : oks;
    // pe pair coefficients for p = lane: (j0i0, j0i1, j1i0, j1i1)
    float4 pp = *(const float4*)&pe[(size_t)gl * 128 + lane * 4];
    float qs0 = qs[2 * lane], qs1 = qs[2 * lane + 1];
    float ks0 = ks[2 * lane], ks1 = ks[2 * lane + 1];
#pragma unroll
    for (int hh = 0; hh < 2; hh++) {
        int h = y * 2 + hh;
        float2 q2 = *(const float2*)&src[h * DH + 2 * lane];
        float2 k2 = *(const float2*)&src[DM + h * DH + 2 * lane];
        float2 v2 = *(const float2*)&src[2 * DM + h * DH + 2 * lane];
        float qss = q2.x * q2.x + q2.y * q2.y;
        float kss = k2.x * k2.x + k2.y * k2.y;
#pragma unroll
        for (int off = 16; off > 0; off >>= 1) {
            qss += __shfl_xor_sync(0xffffffffu, qss, off);
            kss += __shfl_xor_sync(0xffffffffu, kss, off);
        }
        float qinv = rsqrtf(qss * (1.0f / DH) + 1e-6f);
        float kinv = rsqrtf(kss * (1.0f / DH) + 1e-6f);
        float qn0 = q2.x * qinv * qs0, qn1 = q2.y * qinv * qs1;
        float kn0 = k2.x * kinv * ks0, kn1 = k2.y * kinv * ks1;
        // rope: out[2p+j] = pe[p][j][0]*x[2p] + pe[p][j][1]*x[2p+1]
        float qo0 = pp.x * qn0 + pp.y * qn1;
        float qo1 = pp.z * qn0 + pp.w * qn1;
        float ko0 = pp.x * kn0 + pp.y * kn1;
        float ko1 = pp.z * kn0 + pp.w * kn1;
        size_t oidx = ((size_t)h * LT + gl) * DH + 2 * lane;
        // q pre-scaled by 0.125 * log2(e) so softmax can use raw ex2
        *(uint2*)&g_q[oidx] = make_uint2(f2tf(qo0 * 0.18033688f), f2tf(qo1 * 0.18033688f));
        *(uint2*)&g_k[oidx] = make_uint2(f2tf(ko0), f2tf(ko1));
        *(uint2*)&g_v[oidx] = make_uint2(f2tf(v2.x), f2tf(v2.y));
    }
}

// ---------------- attention: flash w/ tf32 mma, in-register softmax, cp.async K/V pipeline ----------------
// 8 warps in 4x2 (wm: 32 q-rows each, wn: 32 cols each). mma m16n8k8. Scores in log2 domain.
#define AS 68   // padded row stride (u32 words)
__global__ __launch_bounds__(256, 2) void attn_mma_kernel() {
    extern __shared__ unsigned smu[];
    unsigned* Qs = smu;                    // [128][AS] tf32
    unsigned* Ks = Qs + 128 * AS;          // [64][AS]  tf32
    unsigned* Vs = Ks + 64 * AS;           // [64][AS]  tf32
    unsigned* Psu = Vs + 64 * AS;          // [128][AS] tf32 probabilities
    float* row_m = (float*)(Psu + 128 * AS);   // [128]
    float* row_l = row_m + 128;                // [128]
    float* wmax = row_l + 128;                 // [2][128] per-warp row max
    float* wsum = wmax + 256;                  // [2][128] per-warp row sum

    int h = blockIdx.x;
    int q0 = blockIdx.y * 128;
    int tid = threadIdx.x;
    int lane = tid & 31, warp = tid >> 5;
    int wm = warp >> 1, wn = warp & 1;     // 4 x 2
    int g = lane >> 2, tg = lane & 3;

    const unsigned* qb = g_q + ((size_t)h * LT + q0) * DH;
    const unsigned* kb = g_k + (size_t)h * LT * DH;
    const unsigned* vb = g_v + (size_t)h * LT * DH;

    unsigned ks_sm = (unsigned)__cvta_generic_to_shared(Ks);
    unsigned vs_sm = (unsigned)__cvta_generic_to_shared(Vs);
    int ld_r = tid >> 4, ld_c = (tid & 15) << 2;

    // load Q tile: 128 rows x 64 words = 2048 uint4 slots
#pragma unroll
    for (int i = 0; i < 8; i++) {
        int idx = tid + i * 256;
        int r = idx >> 4, c = (idx & 15) << 2;
        *(uint4*)&Qs[r * AS + c] = *(const uint4*)&qb[(size_t)r * DH + c];
    }
    if (tid < 128) { row_m[tid] = -3e38f; row_l[tid] = 0.0f; }

    // prologue: async K0, V0 (separate commit groups)
#pragma unroll
    for (int i = 0; i < 4; i++) {
        int r = ld_r + i * 16;
        cp_async16(ks_sm + (r * AS + ld_c) * 4, &kb[(size_t)r * DH + ld_c]);
    }
    asm volatile("cp.async.commit_group;" ::: "memory");
#pragma unroll
    for (int i = 0; i < 4; i++) {
        int r = ld_r + i * 16;
        cp_async16(vs_sm + (r * AS + ld_c) * 4, &vb[(size_t)r * DH + ld_c]);
    }
    asm volatile("cp.async.commit_group;" ::: "memory");

    float acc_o[2][4][4];
#pragma unroll
    for (int mt = 0; mt < 2; mt++)
#pragma unroll
        for (int nt = 0; nt < 4; nt++)
#pragma unroll
            for (int j = 0; j < 4; j++) acc_o[mt][nt][j] = 0.0f;

    for (int kt = 0; kt < LT; kt += 64) {
        int ktn = (kt + 64 < LT) ? kt + 64 : 0;

        asm volatile("cp.async.wait_group 1;" ::: "memory");   // K(t) done
        __syncthreads();                                        // [top] K visible; Psu free

        // ---- S = Q K^T (log2 domain; q pre-scaled) ----
        float acc_s[2][4][4];
#pragma unroll
        for (int mt = 0; mt < 2; mt++)
#pragma unroll
            for (int nt = 0; nt < 4; nt++)
#pragma unroll
                for (int j = 0; j < 4; j++) acc_s[mt][nt][j] = 0.0f;
#pragma unroll
        for (int k8 = 0; k8 < 8; k8++) {
            unsigned a[2][4], b[4][2];
#pragma unroll
            for (int mt = 0; mt < 2; mt++) {
                int r = wm * 32 + mt * 16;
                a[mt][0] = Qs[(r + g) * AS + k8 * 8 + tg];
                a[mt][1] = Qs[(r + 8 + g) * AS + k8 * 8 + tg];
                a[mt][2] = Qs[(r + g) * AS + k8 * 8 + tg + 4];
                a[mt][3] = Qs[(r + 8 + g) * AS + k8 * 8 + tg + 4];
            }
#pragma unroll
            for (int nt = 0; nt < 4; nt++) {
                int c = wn * 32 + nt * 8 + g;
                b[nt][0] = Ks[c * AS + k8 * 8 + tg];
                b[nt][1] = Ks[c * AS + k8 * 8 + tg + 4];
            }
#pragma unroll
            for (int mt = 0; mt < 2; mt++)
#pragma unroll
                for (int nt = 0; nt < 4; nt++)
                    mma_tf32(acc_s[mt][nt], a[mt], b[nt]);
        }

        // ---- per-warp row max via shuffles over tg lanes ----
#pragma unroll
        for (int mt = 0; mt < 2; mt++)
#pragma unroll
            for (int half = 0; half < 2; half++) {
                float m = acc_s[mt][0][half * 2];
#pragma unroll
                for (int nt = 0; nt < 4; nt++) {
                    m = fmaxf(m, acc_s[mt][nt][half * 2 + 0]);
                    m = fmaxf(m, acc_s[mt][nt][half * 2 + 1]);
                }
                m = fmaxf(m, __shfl_xor_sync(0xffffffffu, m, 1));
                m = fmaxf(m, __shfl_xor_sync(0xffffffffu, m, 2));
                if (tg == 0) wmax[wn * 128 + wm * 32 + mt * 16 + half * 8 + g] = m;
            }
        __syncthreads();                                        // [A] wmax ready; Ks free

        // issue K(t+1) (overlaps softmax + PV)
#pragma unroll
        for (int i = 0; i < 4; i++) {
            int r = ld_r + i * 16;
            cp_async16(ks_sm + (r * AS + ld_c) * 4, &kb[(size_t)(ktn + r) * DH + ld_c]);
        }
        asm volatile("cp.async.commit_group;" ::: "memory");

        // ---- in-register softmax: exp2, P -> tf32 smem, row sums via shuffles ----
        float mnew[2][2], corr[2][2];
#pragma unroll
        for (int mt = 0; mt < 2; mt++)
#pragma unroll
            for (int half = 0; half < 2; half++) {
                int r = wm * 32 + mt * 16 + half * 8 + g;
                float mo = row_m[r];
                float mn = fmaxf(mo, fmaxf(wmax[r], wmax[128 + r]));
                float cr = fexp2(mo - mn);
                mnew[mt][half] = mn; corr[mt][half] = cr;
                float ps = 0.0f;
#pragma unroll
                for (int nt = 0; nt < 4; nt++) {
                    float p0 = fexp2(acc_s[mt][nt][half * 2 + 0] - mn);
                    float p1 = fexp2(acc_s[mt][nt][half * 2 + 1] - mn);
                    ps += p0 + p1;
                    int c = wn * 32 + nt * 8 + 2 * tg;
                    Psu[r * AS + c]     = f2tf(p0);
                    Psu[r * AS + c + 1] = f2tf(p1);
                }
                ps += __shfl_xor_sync(0xffffffffu, ps, 1);
                ps += __shfl_xor_sync(0xffffffffu, ps, 2);
                if (tg == 0) wsum[wn * 128 + r] = ps;
                // rescale O
#pragma unroll
                for (int nt = 0; nt < 4; nt++) {
                    acc_o[mt][nt][half * 2 + 0] *= cr;
                    acc_o[mt][nt][half * 2 + 1] *= cr;
                }
            }
        asm volatile("cp.async.wait_group 1;" ::: "memory");   // V(t) done (K(t+1) pends)
        __syncthreads();                                        // [B] Psu/wsum complete, V visible

        // designated lanes update running stats (overlaps PV mma on other lanes)
        if (wn == 0 && tg == 0) {
#pragma unroll
            for (int mt = 0; mt < 2; mt++)
#pragma unroll
                for (int half = 0; half < 2; half++) {
                    int r = wm * 32 + mt * 16 + half * 8 + g;
                    row_l[r] = row_l[r] * corr[mt][half] + wsum[r] + wsum[128 + r];
                    row_m[r] = mnew[mt][half];
                }
        }

        // ---- O += P V ----
#pragma unroll
        for (int k8 = 0; k8 < 8; k8++) {
            unsigned a[2][4], b[4][2];
#pragma unroll
            for (int mt = 0; mt < 2; mt++) {
                int r = wm * 32 + mt * 16;
                a[mt][0] = Psu[(r + g) * AS + k8 * 8 + tg];
                a[mt][1] = Psu[(r + 8 + g) * AS + k8 * 8 + tg];
                a[mt][2] = Psu[(r + g) * AS + k8 * 8 + tg + 4];
                a[mt][3] = Psu[(r + 8 + g) * AS + k8 * 8 + tg + 4];
            }
#pragma unroll
            for (int nt = 0; nt < 4; nt++) {
                int c = wn * 32 + nt * 8 + g;          // output col (d)
                b[nt][0] = Vs[(k8 * 8 + tg) * AS + c];
                b[nt][1] = Vs[(k8 * 8 + tg + 4) * AS + c];
            }
#pragma unroll
            for (int mt = 0; mt < 2; mt++)
#pragma unroll
                for (int nt = 0; nt < 4; nt++)
                    mma_tf32(acc_o[mt][nt], a[mt], b[nt]);
        }
        __syncthreads();                            // [C] Vs reads done

        // issue V(t+1) (overlaps next tile's S-mma)
#pragma unroll
        for (int i = 0; i < 4; i++) {
            int r = ld_r + i * 16;
            cp_async16(vs_sm + (r * AS + ld_c) * 4, &vb[(size_t)(ktn + r) * DH + ld_c]);
        }
        asm volatile("cp.async.commit_group;" ::: "memory");
    }
    asm volatile("cp.async.wait_group 0;" ::: "memory");
    __syncthreads();

    // epilogue: normalize by row_l, write out
#pragma unroll
    for (int mt = 0; mt < 2; mt++)
#pragma unroll
        for (int half = 0; half < 2; half++) {
            int r = wm * 32 + mt * 16 + half * 8 + g;
            float inv = 1.0f / row_l[r];
#pragma unroll
            for (int nt = 0; nt < 4; nt++) {
                int c = wn * 32 + nt * 8 + 2 * tg;
                float* dst = &g_attn[(size_t)(q0 + r) * DM + h * DH + c];
                dst[0] = acc_o[mt][nt][half * 2 + 0] * inv;
                dst[1] = acc_o[mt][nt][half * 2 + 1] * inv;
            }
        }
}

// ---------------- launch ----------------
extern "C" void kernel_launch(void* const* d_in, const int* in_sizes, int n_in,
                              void* d_out, int out_size) {
    const float* obs   = (const float*)d_in[0];
    const float* cond  = (const float*)d_in[1];
    const float* vec   = (const float*)d_in[2];
    const float* pe    = (const float*)d_in[3];
    const float* o_mod_w = (const float*)d_in[4];
    const float* o_mod_b = (const float*)d_in[5];
    const float* o_qkv_w = (const float*)d_in[6];
    const float* o_q_s   = (const float*)d_in[7];
    const float* o_k_s   = (const float*)d_in[8];
    const float* o_proj_w = (const float*)d_in[9];
    const float* o_proj_b = (const float*)d_in[10];
    const float* o_mlp_w1 = (const float*)d_in[11];
    const float* o_mlp_b1 = (const float*)d_in[12];
    const float* o_mlp_w2 = (const float*)d_in[13];
    const float* o_mlp_b2 = (const float*)d_in[14];
    const float* c_mod_w = (const float*)d_in[15];
    const float* c_mod_b = (const float*)d_in[16];
    const float* c_qkv_w = (const float*)d_in[17];
    const float* c_q_s   = (const float*)d_in[18];
    const float* c_k_s   = (const float*)d_in[19];
    const float* c_proj_w = (const float*)d_in[20];
    const float* c_proj_b = (const float*)d_in[21];
    const float* c_mlp_w1 = (const float*)d_in[22];
    const float* c_mlp_b1 = (const float*)d_in[23];
    const float* c_mlp_w2 = (const float*)d_in[24];
    const float* c_mlp_b2 = (const float*)d_in[25];

    float* out = (float*)d_out;
    float* out_obs = out;                 // rows 0..LO-1
    float* out_cond = out + (size_t)LO * DM;

    float *p_xm, *p_qkv, *p_attn, *p_h;
    cudaGetSymbolAddress((void**)&p_xm, g_xm);
    cudaGetSymbolAddress((void**)&p_qkv, g_qkv);
    cudaGetSymbolAddress((void**)&p_attn, g_attn);
    cudaGetSymbolAddress((void**)&p_h, g_h);

    int smem_bytes = (int)((384 * AS) * 4 + (128 + 128 + 256 + 256) * 4);
    static int init = 0;
    if (!init) {
        init = 1;
        cudaFuncSetAttribute(attn_mma_kernel, cudaFuncAttributeMaxDynamicSharedMemorySize, smem_bytes);
    }

    // 1. modulation vectors (K-split for parallelism)
    mod_kernel<<<192, 256>>>(vec, o_mod_w, o_mod_b, c_mod_w, c_mod_b);

    // 2. LN + mod (chunks: 0=shift1, 1=scale1), merged
    ln_mod_kernel<<<LT, 256>>>(obs, cond, p_xm, 0, 1);

    // 3. qkv GEMMs, merged
    {
        dim3 g(3 * DM / 128, LT / 128);
        mma_gemm2_kernel<<<g, 256>>>(p_xm, o_qkv_w, p_qkv,
                                     p_xm + (size_t)LO * DM, c_qkv_w, p_qkv + (size_t)LO * 3 * DM,
                                     LO, 3 * DM, DM,
                                     nullptr, nullptr, nullptr, nullptr, -1, -1, 0);
    }

    // 4. rmsnorm + rope + scatter (tf32 pre-converted, warp-per-head)
    {
        dim3 b(32, 8);
        qkv_post_kernel<<<LT, b>>>(pe, o_q_s, o_k_s, c_q_s, c_k_s);
    }

    // 5. attention (tensor-core flash, cp.async pipelined, in-register softmax)
    {
        dim3 g(NH, LT / 128);
        attn_mma_kernel<<<g, 256, smem_bytes>>>();
    }

    // 6. proj + gated residual (gate1 = chunk 2), merged
    {
        dim3 g(DM / 128, LT / 128);
        mma_gemm2_kernel<<<g, 256>>>(p_attn + (size_t)LC * DM, o_proj_w, out_obs,
                                     p_attn, c_proj_w, out_cond,
                                     LO, DM, DM,
                                     o_proj_b, c_proj_b, obs, cond, 0 * 6 + 2, 1 * 6 + 2, 1);
    }

    // 7. LN2 + mod (chunks: 3=shift2, 4=scale2), merged
    ln_mod_kernel<<<LT, 256>>>(out_obs, out_cond, p_xm, 3, 4);

    // 8. mlp1 + gelu, merged
    {
        dim3 g(MH / 128, LT / 128);
        mma_gemm2_kernel<<<g, 256>>>(p_xm, o_mlp_w1, p_h,
                                     p_xm + (size_t)LO * DM, c_mlp_w1, p_h + (size_t)LO * MH,
                                     LO, MH, DM,
                                     o_mlp_b1, c_mlp_b1, nullptr, nullptr, -1, -1, 2);
    }

    // 9. mlp2 + gated residual (gate2 = chunk 5), merged, in-place residual on d_out
    {
        dim3 g(DM / 128, LT / 128);
        mma_gemm2_kernel<<<g, 256>>>(p_h, o_mlp_w2, out_obs,
                                     p_h + (size_t)LO * MH, c_mlp_w2, out_cond,
                                     LO, DM, MH,
                                     o_mlp_b2, c_mlp_b2, out_obs, out_cond, 0 * 6 + 5, 1 * 6 + 5, 1);
    }
}